// round 2
// baseline (speedup 1.0000x reference)
#include <cuda_runtime.h>
#include <cuda_bf16.h>
#include <cstdint>
#include <cstddef>

// ---------------------------------------------------------------------------
// QuantizedLinear via int8 mma.sync (base sm_100 ISA; tcgen05 unavailable —
// harness PTX target is compute_100 without the 'a' feature set).
//
// out[m,n] = acc[m,n]*alpha[n] + beta[n]
//   acc    = sum_k q(x[m,k]) * w[n,k]            (exact s32)
//   q(x)   = clamp(rint(x/sa + zp), -128, 127)
//   alpha  = ws[n]*sa
//   beta   = bias[n] - zp*(sum_k w[n,k])*alpha
//
// Pass 1a: quantize x fp32 -> s8 into g_A
// Pass 1b: weights s32 -> s8 into g_W; alpha/beta
// Pass 2 : 128x128 CTA tile GEMM, K chunks of 64B, 4-stage cp.async,
//          mma.sync.m16n8k32.s8, fused epilogue.
// ---------------------------------------------------------------------------

#define K_DIM    1024
#define N_DIM    1024
#define M_MAX    16384
#define M_TILE   128
#define N_TILE   128
#define K_TILE   64
#define K_CHUNKS (K_DIM / K_TILE)        // 16
#define STAGES   4
#define THREADS  256

#define SMEM_STRIDE 80                    // 64B row + 16B pad (conflict-free quads)
#define A_BYTES   (M_TILE * SMEM_STRIDE)  // 10240
#define B_BYTES   (N_TILE * SMEM_STRIDE)  // 10240
#define STAGE_BYTES (A_BYTES + B_BYTES)   // 20480
#define SMEM_TOTAL (STAGES * STAGE_BYTES) // 81920

__device__ __align__(16) int8_t g_A[(size_t)M_MAX * K_DIM];  // 16 MB
__device__ __align__(16) int8_t g_W[(size_t)N_DIM * K_DIM];  //  1 MB
__device__ float g_alpha[N_DIM];
__device__ float g_beta[N_DIM];

// ------------------------------- PTX helpers -------------------------------

__device__ __forceinline__ uint32_t smem_u32(const void* p) {
    return (uint32_t)__cvta_generic_to_shared(p);
}
__device__ __forceinline__ void cp_async16(uint32_t dst, const void* src) {
    asm volatile("cp.async.cg.shared.global [%0], [%1], 16;"
                 :: "r"(dst), "l"(src) : "memory");
}
__device__ __forceinline__ void cp_commit() {
    asm volatile("cp.async.commit_group;" ::: "memory");
}
__device__ __forceinline__ void cp_wait3() {
    asm volatile("cp.async.wait_group 3;" ::: "memory");
}
__device__ __forceinline__ void mma_s8(int* c, uint32_t a0, uint32_t a1,
                                       uint32_t a2, uint32_t a3,
                                       uint32_t b0, uint32_t b1) {
    asm volatile(
        "mma.sync.aligned.m16n8k32.row.col.s32.s8.s8.s32 "
        "{%0,%1,%2,%3}, {%4,%5,%6,%7}, {%8,%9}, {%0,%1,%2,%3};"
        : "+r"(c[0]), "+r"(c[1]), "+r"(c[2]), "+r"(c[3])
        : "r"(a0), "r"(a1), "r"(a2), "r"(a3), "r"(b0), "r"(b1));
}
__device__ __forceinline__ uint32_t lds32(uint32_t addr) {
    uint32_t v;
    asm volatile("ld.shared.b32 %0, [%1];" : "=r"(v) : "r"(addr));
    return v;
}

// --------------------------- Pass 1a: quantize x ---------------------------
// mul-then-add (no FMA contraction) to match jnp; rintf = round-half-even
// matches jnp.round.

__global__ void quantize_kernel(const float* __restrict__ x,
                                const float* __restrict__ act_scale,
                                const float* __restrict__ act_zp,
                                int n4) {
    float inv = 1.0f / act_scale[0];
    float zp  = act_zp[0];
    int stride = gridDim.x * blockDim.x;
    for (int i = blockIdx.x * blockDim.x + threadIdx.x; i < n4; i += stride) {
        float4 v = reinterpret_cast<const float4*>(x)[i];
        int q0 = (int)fminf(fmaxf(rintf(__fadd_rn(__fmul_rn(v.x, inv), zp)), -128.f), 127.f);
        int q1 = (int)fminf(fmaxf(rintf(__fadd_rn(__fmul_rn(v.y, inv), zp)), -128.f), 127.f);
        int q2 = (int)fminf(fmaxf(rintf(__fadd_rn(__fmul_rn(v.z, inv), zp)), -128.f), 127.f);
        int q3 = (int)fminf(fmaxf(rintf(__fadd_rn(__fmul_rn(v.w, inv), zp)), -128.f), 127.f);
        uint32_t p = (uint32_t)(q0 & 0xFF) | ((uint32_t)(q1 & 0xFF) << 8) |
                     ((uint32_t)(q2 & 0xFF) << 16) | ((uint32_t)(q3 & 0xFF) << 24);
        reinterpret_cast<uint32_t*>(g_A)[i] = p;
    }
}

// ------------------------- Pass 1b: weight prep ----------------------------

__global__ void prep_weights_kernel(const int* __restrict__ w,
                                    const float* __restrict__ wscales,
                                    const float* __restrict__ ascale,
                                    const float* __restrict__ azp,
                                    const float* __restrict__ bias) {
    int o = blockIdx.x;          // 0..1023
    int t = threadIdx.x;         // 0..127
    const int* row = w + (size_t)o * K_DIM;
    float sum = 0.f;
    for (int i = t * 4; i < K_DIM; i += 128 * 4) {
        int4 v = *reinterpret_cast<const int4*>(row + i);
        sum += (float)(v.x + v.y + v.z + v.w);
        uint32_t p = (uint32_t)(v.x & 0xFF) | ((uint32_t)(v.y & 0xFF) << 8) |
                     ((uint32_t)(v.z & 0xFF) << 16) | ((uint32_t)(v.w & 0xFF) << 24);
        reinterpret_cast<uint32_t*>(g_W + (size_t)o * K_DIM + i)[0] = p;
    }
    __shared__ float red[128];
    red[t] = sum;
    __syncthreads();
    for (int s = 64; s > 0; s >>= 1) {
        if (t < s) red[t] += red[t + s];
        __syncthreads();
    }
    if (t == 0) {
        float alpha = wscales[o] * ascale[0];
        g_alpha[o] = alpha;
        g_beta[o]  = bias[o] - azp[0] * red[0] * alpha;
    }
}

// ----------------------------- Pass 2: GEMM --------------------------------
// 8 warps in 4(M) x 2(N); warp tile 32 x 64.
// mma m16n8k32 fragment maps (lane g = lane>>2, q = lane&3):
//   A a0: (row g,   k 4q..4q+3)   a1: (g+8, 4q)   a2: (g, 16+4q)  a3: (g+8, 16+4q)
//   B b0: (k 4q, col g)           b1: (k 16+4q, col g)
//   C c0,c1: (row g,   col 2q,2q+1)  c2,c3: (row g+8, ...)

__global__ __launch_bounds__(THREADS)
void gemm_kernel(float* __restrict__ out) {
    extern __shared__ char smem[];
    uint32_t sbase = smem_u32(smem);

    const int tid = threadIdx.x;
    const int wid = tid >> 5;
    const int lane = tid & 31;
    const int g = lane >> 2;       // group id
    const int q = lane & 3;        // thread in group

    const int bid = blockIdx.x;
    const int m0 = (bid >> 3) * M_TILE;
    const int n0 = (bid & 7) * N_TILE;

    const int wm = wid & 3;        // warp M index (0..3)
    const int wn = wid >> 2;       // warp N index (0..1)

    // ---- per-thread cp.async job table: 4 x 16B chunks per stage ----
    // chunks 0..511 -> A (128 rows x 4), 512..1023 -> B
    const int8_t* src[4];
    uint32_t dst[4];
#pragma unroll
    for (int j = 0; j < 4; j++) {
        int c = tid + j * THREADS;
        if (c < 512) {
            int r = c >> 2, t = c & 3;
            src[j] = g_A + (size_t)(m0 + r) * K_DIM + t * 16;
            dst[j] = (uint32_t)(r * SMEM_STRIDE + t * 16);
        } else {
            int cc = c - 512;
            int r = cc >> 2, t = cc & 3;
            src[j] = g_W + (size_t)(n0 + r) * K_DIM + t * 16;
            dst[j] = (uint32_t)(A_BYTES + r * SMEM_STRIDE + t * 16);
        }
    }
    auto load_chunk = [&](int kc) {
        uint32_t stage = sbase + (uint32_t)(kc & (STAGES - 1)) * STAGE_BYTES;
#pragma unroll
        for (int j = 0; j < 4; j++)
            cp_async16(stage + dst[j], src[j] + kc * K_TILE);
    };

    // prologue
#pragma unroll
    for (int k = 0; k < STAGES - 1; k++) { load_chunk(k); cp_commit(); }

    int acc[2][8][4];
#pragma unroll
    for (int mf = 0; mf < 2; mf++)
#pragma unroll
        for (int nf = 0; nf < 8; nf++)
#pragma unroll
            for (int i = 0; i < 4; i++) acc[mf][nf][i] = 0;

    // per-warp smem base offsets (within stage)
    const uint32_t a_row0 = (uint32_t)((wm * 32 + g) * SMEM_STRIDE + 4 * q);
    const uint32_t b_col0 = (uint32_t)(A_BYTES + (wn * 64 + g) * SMEM_STRIDE + 4 * q);

    for (int kc = 0; kc < K_CHUNKS; kc++) {
        int kl = kc + STAGES - 1;
        if (kl < K_CHUNKS) load_chunk(kl);
        cp_commit();
        cp_wait3();
        __syncthreads();

        uint32_t stage = sbase + (uint32_t)(kc & (STAGES - 1)) * STAGE_BYTES;
#pragma unroll
        for (int ks = 0; ks < 2; ks++) {          // two k=32 steps per 64B chunk
            uint32_t ko = (uint32_t)(ks * 32);
            uint32_t a[2][4];
#pragma unroll
            for (int mf = 0; mf < 2; mf++) {
                uint32_t r = stage + a_row0 + (uint32_t)(mf * 16 * SMEM_STRIDE) + ko;
                a[mf][0] = lds32(r);
                a[mf][1] = lds32(r + 8 * SMEM_STRIDE);
                a[mf][2] = lds32(r + 16);
                a[mf][3] = lds32(r + 8 * SMEM_STRIDE + 16);
            }
#pragma unroll
            for (int nf = 0; nf < 8; nf++) {
                uint32_t bb = stage + b_col0 + (uint32_t)(nf * 8 * SMEM_STRIDE) + ko;
                uint32_t b0 = lds32(bb);
                uint32_t b1 = lds32(bb + 16);
#pragma unroll
                for (int mf = 0; mf < 2; mf++)
                    mma_s8(acc[mf][nf], a[mf][0], a[mf][1], a[mf][2], a[mf][3], b0, b1);
            }
        }
        __syncthreads();
    }

    // ---- epilogue: y = acc*alpha[n] + beta[n], float2 stores ----
#pragma unroll
    for (int nf = 0; nf < 8; nf++) {
        int col = n0 + wn * 64 + nf * 8 + 2 * q;
        float2 al = *reinterpret_cast<const float2*>(&g_alpha[col]);
        float2 be = *reinterpret_cast<const float2*>(&g_beta[col]);
#pragma unroll
        for (int mf = 0; mf < 2; mf++) {
            int row = m0 + wm * 32 + mf * 16 + g;
            float2 v0, v1;
            v0.x = (float)acc[mf][nf][0] * al.x + be.x;
            v0.y = (float)acc[mf][nf][1] * al.y + be.y;
            v1.x = (float)acc[mf][nf][2] * al.x + be.x;
            v1.y = (float)acc[mf][nf][3] * al.y + be.y;
            *reinterpret_cast<float2*>(out + (size_t)row * N_DIM + col) = v0;
            *reinterpret_cast<float2*>(out + (size_t)(row + 8) * N_DIM + col) = v1;
        }
    }
}

// ------------------------------- launcher ----------------------------------

extern "C" void kernel_launch(void* const* d_in, const int* in_sizes, int n_in,
                              void* d_out, int out_size) {
    const float* x    = (const float*)d_in[0];   // [B,S,IN] fp32
    const int*   wint = (const int*)  d_in[1];   // [OUT,IN] int32
    const float* wsc  = (const float*)d_in[2];   // [OUT]
    const float* asc  = (const float*)d_in[3];   // [1]
    const float* azp  = (const float*)d_in[4];   // [1]
    const float* bias = (const float*)d_in[5];   // [OUT]
    float* out = (float*)d_out;

    int M  = in_sizes[0] / K_DIM;                // 16384
    int n4 = in_sizes[0] / 4;

    cudaFuncSetAttribute(gemm_kernel,
                         cudaFuncAttributeMaxDynamicSharedMemorySize, SMEM_TOTAL);

    quantize_kernel<<<2048, 256>>>(x, asc, azp, n4);
    prep_weights_kernel<<<N_DIM, 128>>>(wint, wsc, asc, azp, bias);
    gemm_kernel<<<(M / M_TILE) * (N_DIM / N_TILE), THREADS, SMEM_TOTAL>>>(out);
}